// round 10
// baseline (speedup 1.0000x reference)
#include <cuda_runtime.h>
#include <cuda_bf16.h>
#include <cstdint>

typedef unsigned long long ull;

#define NB   256
#define TT   254
#define AUGS 148
#define CH   145
#define SIGK 21170
#define SIGS 21312          // padded K: 37*576, mult of 32
#define SPLITK 37
#define KCH  576
#define NCH  18             // 576/32 chunks
#define RST  40             // smem row stride in halves (conflict-free)
#define ARR_B (128 * RST * 2)
#define BUF_B (4 * ARR_B)

__device__ float g_aug[NB * TT * AUGS];
__device__ __align__(16) __nv_bfloat16 g_shi[(size_t)NB * SIGS];
__device__ __align__(16) __nv_bfloat16 g_slo[(size_t)NB * SIGS];
__device__ __align__(16) __nv_bfloat16 g_whi[(size_t)256 * SIGS];
__device__ __align__(16) __nv_bfloat16 g_wlo[(size_t)256 * SIGS];
__device__ float g_part[(size_t)SPLITK * 256 * 256];

__device__ __forceinline__ ull pack2(float lo, float hi) {
    ull r; asm("mov.b64 %0, {%1, %2};" : "=l"(r) : "f"(lo), "f"(hi)); return r;
}
__device__ __forceinline__ void unpack2(ull v, float& lo, float& hi) {
    asm("mov.b64 {%0, %1}, %2;" : "=f"(lo), "=f"(hi) : "l"(v));
}
__device__ __forceinline__ void ffma2(ull& acc, ull a, ull b) {
    asm("fma.rn.f32x2 %0, %1, %2, %0;" : "+l"(acc) : "l"(a), "l"(b));
}
__device__ __forceinline__ uint32_t smem_u32(const void* p) {
    uint32_t a;
    asm("{ .reg .u64 t; cvta.to.shared.u64 t, %1; cvt.u32.u64 %0, t; }"
        : "=r"(a) : "l"(p));
    return a;
}
__device__ __forceinline__ uint32_t ld32h(const __nv_bfloat16* p) {
    return *(const uint32_t*)p;
}
__device__ __forceinline__ void mma16816(float* d, const uint32_t* a,
                                         const uint32_t* b) {
    asm volatile(
        "mma.sync.aligned.m16n8k16.row.col.f32.bf16.bf16.f32 "
        "{%0,%1,%2,%3}, {%4,%5,%6,%7}, {%8,%9}, {%0,%1,%2,%3};"
        : "+f"(d[0]), "+f"(d[1]), "+f"(d[2]), "+f"(d[3])
        : "r"(a[0]), "r"(a[1]), "r"(a[2]), "r"(a[3]), "r"(b[0]), "r"(b[1]));
}
__device__ __forceinline__ void st_split(__nv_bfloat16* ph, __nv_bfloat16* pl, float v) {
    __nv_bfloat16 h = __float2bfloat16(v);
    *ph = h;
    *pl = __float2bfloat16(v - __bfloat162float(h));
}

// ============================================================
// K1: conv1(3,16->64) + conv2(1x1,64->128,relu) -> g_aug
// ============================================================
#define HS 72
__global__ __launch_bounds__(256, 2) void k_front(
    const float* __restrict__ q,
    const float* __restrict__ w1, const float* __restrict__ b1,
    const float* __restrict__ w2, const float* __restrict__ b2)
{
    extern __shared__ float sm[];
    float* sXd = sm;
    float* sW1 = sm + 8192;
    float* sW2 = sm + 11264;
    float* sH  = sm + 19456;
    float* sB1 = sm + 24064;
    float* sB2 = sm + 24128;

    int n = blockIdx.x, tid = threadIdx.x;
    int b = n >> 3, hh = n & 7;

    for (int idx = tid; idx < 4096; idx += 256) {
        int t = idx >> 4, e = idx & 15;
        float v = q[(((size_t)b * 256 + t) * 8 + hh) * 16 + e];
        *(ull*)&sXd[2 * idx] = pack2(v, v);
    }
    for (int idx = tid; idx < 3072; idx += 256) sW1[idx] = w1[idx];
    for (int idx = tid; idx < 8192; idx += 256) sW2[idx] = w2[idx];
    if (tid < 64) sB1[tid] = b1[tid];
    else if (tid < 192) sB2[tid - 64] = b2[tid - 64];
    __syncthreads();

    float* aug = g_aug + (size_t)n * (TT * AUGS);

    for (int t = tid >> 5; t < TT; t += 8) {
        for (int c = tid & 31; c < 17; c += 32) {
            aug[t * AUGS + c] = (c < 16) ? sXd[2 * ((t + 2) * 16 + c)]
                                         : (float)t * (1.0f / 253.0f);
        }
    }

    int mg = tid & 7,  tg  = tid >> 3;
    int cg = tid & 15, tgq = tid >> 4;

    for (int t0 = 0; t0 < TT; t0 += 64) {
        int tc = min(64, TT - t0);
        __syncthreads();
        {
            ull acc[2][4];
            #pragma unroll
            for (int j = 0; j < 4; j++) {
                ull bia = pack2(sB1[2 * (mg + 8 * j)], sB1[2 * (mg + 8 * j) + 1]);
                acc[0][j] = bia; acc[1][j] = bia;
            }
            const ull* xr0 = (const ull*)sXd + (t0 + 2 * tg) * 16;
            const ull* xr1 = xr0 + 16;
            #pragma unroll
            for (int we = 0; we < 48; we++) {
                ull xa = xr0[we], xb = xr1[we];
                #pragma unroll
                for (int j = 0; j < 4; j++) {
                    ull wv = *(const ull*)&sW1[we * 64 + 2 * (mg + 8 * j)];
                    ffma2(acc[0][j], xa, wv);
                    ffma2(acc[1][j], xb, wv);
                }
            }
            #pragma unroll
            for (int tl = 0; tl < 2; tl++) {
                int t = 2 * tg + tl;
                if (t < tc) {
                    float* hr = &sH[t * HS];
                    #pragma unroll
                    for (int j = 0; j < 4; j++)
                        *(ull*)&hr[2 * (mg + 8 * j)] = acc[tl][j];
                }
            }
        }
        __syncthreads();
        {
            ull acc[4][4];
            #pragma unroll
            for (int j = 0; j < 4; j++) {
                ull bia = pack2(sB2[2 * (cg + 16 * j)], sB2[2 * (cg + 16 * j) + 1]);
                #pragma unroll
                for (int i = 0; i < 4; i++) acc[i][j] = bia;
            }
            #pragma unroll
            for (int m = 0; m < 64; m++) {
                ull wv[4];
                #pragma unroll
                for (int j = 0; j < 4; j++)
                    wv[j] = *(const ull*)&sW2[m * 128 + 2 * (cg + 16 * j)];
                #pragma unroll
                for (int i = 0; i < 4; i++) {
                    float h = sH[(4 * tgq + i) * HS + m];
                    ull hv = pack2(h, h);
                    #pragma unroll
                    for (int j = 0; j < 4; j++) ffma2(acc[i][j], hv, wv[j]);
                }
            }
            #pragma unroll
            for (int i = 0; i < 4; i++) {
                int t = 4 * tgq + i;
                if (t < tc) {
                    float* ar = aug + (size_t)(t0 + t) * AUGS + 17;
                    #pragma unroll
                    for (int j = 0; j < 4; j++) {
                        float lo, hi; unpack2(acc[i][j], lo, hi);
                        int c = 2 * (cg + 16 * j);
                        ar[c]     = fmaxf(lo, 0.f);
                        ar[c + 1] = fmaxf(hi, 0.f);
                    }
                }
            }
        }
    }
}

// ============================================================
// K2: signature -> bf16 hi/lo sig rows
// ============================================================
__global__ __launch_bounds__(256) void k_sig()
{
    __shared__ float sD[2][8][168];
    __shared__ float sU[2][8][168];
    __shared__ float sA0[168];

    int n = blockIdx.x, tid = threadIdx.x;
    const float* aug = g_aug + (size_t)n * (TT * AUGS);
    __nv_bfloat16* sh = g_shi + (size_t)n * SIGS;
    __nv_bfloat16* sl = g_slo + (size_t)n * SIGS;

    if (tid < 168) sA0[tid] = (tid < CH) ? aug[tid] : 0.f;
    if (tid < CH) {
        float v = aug[253 * AUGS + tid] - aug[tid];   // s1
        st_split(sh + tid, sl + tid, v);
    }
    for (int i = SIGK + tid; i < SIGS; i += 256) {    // zero K pads
        sh[i] = __float2bfloat16(0.f);
        sl[i] = __float2bfloat16(0.f);
    }

    int kk = tid >> 5, cx = tid & 31;
    int ty = tid >> 4, tx = tid & 15;

    float pa[5], pb[5];
    {
        const float* rr = aug + (size_t)kk * AUGS;
        #pragma unroll
        for (int s = 0; s < 5; s++) {
            int c = cx + 32 * s;
            bool ok = (c < CH);
            pa[s] = ok ? rr[c] : 0.f;
            pb[s] = ok ? rr[AUGS + c] : 0.f;
        }
    }
    __syncthreads();
    #pragma unroll
    for (int s = 0; s < 5; s++) {
        int c = cx + 32 * s;
        sD[0][kk][c] = pb[s] - pa[s];
        sU[0][kk][c] = 0.5f * (pa[s] + pb[s]) - sA0[c];
    }
    __syncthreads();

    ull acc[10][5];
    #pragma unroll
    for (int r = 0; r < 10; r++)
        #pragma unroll
        for (int s = 0; s < 5; s++) acc[r][s] = 0ull;

    for (int it = 0; it < 32; it++) {
        int cur = it & 1;
        float na[5], nb[5];
        if (it + 1 < 32) {
            int t = 8 * (it + 1) + kk;
            bool tok = (t < 253);
            const float* rr = aug + (size_t)(tok ? t : 0) * AUGS;
            #pragma unroll
            for (int s = 0; s < 5; s++) {
                int c = cx + 32 * s;
                bool ok = tok && (c < CH);
                na[s] = ok ? rr[c] : 0.f;
                nb[s] = ok ? rr[AUGS + c] : 0.f;
            }
        }
        #pragma unroll
        for (int k2 = 0; k2 < 8; k2++) {
            ull d2[5];
            #pragma unroll
            for (int s = 0; s < 5; s++)
                d2[s] = *(const ull*)&sD[cur][k2][2 * (tx + 16 * s)];
            #pragma unroll
            for (int r = 0; r < 10; r++) {
                float u = sU[cur][k2][ty + 16 * r];
                ull uu = pack2(u, u);
                #pragma unroll
                for (int s = 0; s < 5; s++) ffma2(acc[r][s], uu, d2[s]);
            }
        }
        if (it + 1 < 32) {
            int nxt = cur ^ 1;
            #pragma unroll
            for (int s = 0; s < 5; s++) {
                int c = cx + 32 * s;
                sD[nxt][kk][c] = nb[s] - na[s];
                sU[nxt][kk][c] = 0.5f * (na[s] + nb[s]) - sA0[c];
            }
        }
        __syncthreads();
    }

    #pragma unroll
    for (int r = 0; r < 10; r++) {
        int i = ty + 16 * r;
        if (i >= CH) continue;
        int rowb = 145 + i * 145;
        #pragma unroll
        for (int s = 0; s < 5; s++) {
            int j = 2 * (tx + 16 * s);
            float lo, hi; unpack2(acc[r][s], lo, hi);
            if (j < CH)     st_split(sh + rowb + j,     sl + rowb + j,     lo);
            if (j + 1 < CH) st_split(sh + rowb + j + 1, sl + rowb + j + 1, hi);
        }
    }
}

// ============================================================
// K3: W prep — transpose lin_w[21170][256] -> bf16 hi/lo [o][k]
// ============================================================
__global__ __launch_bounds__(256) void k_wprep(const float* __restrict__ W)
{
    __shared__ float sw[32 * 256];
    int k0 = blockIdx.x * 32, tid = threadIdx.x;
    for (int r = 0; r < 32; r++) {
        int k = k0 + r;
        sw[r * 256 + tid] = (k < SIGK) ? W[(size_t)k * 256 + tid] : 0.f;
    }
    __syncthreads();
    __nv_bfloat16* dh = g_whi + (size_t)tid * SIGS + k0;
    __nv_bfloat16* dl = g_wlo + (size_t)tid * SIGS + k0;
    for (int r = 0; r < 32; r += 8) {
        unsigned hu[4], lu[4];
        #pragma unroll
        for (int j = 0; j < 4; j++) {
            float v0 = sw[(r + 2 * j) * 256 + tid];
            float v1 = sw[(r + 2 * j + 1) * 256 + tid];
            __nv_bfloat16 h0 = __float2bfloat16(v0), h1 = __float2bfloat16(v1);
            __nv_bfloat16 l0 = __float2bfloat16(v0 - __bfloat162float(h0));
            __nv_bfloat16 l1 = __float2bfloat16(v1 - __bfloat162float(h1));
            hu[j] = (unsigned)__bfloat16_as_ushort(h0) |
                    ((unsigned)__bfloat16_as_ushort(h1) << 16);
            lu[j] = (unsigned)__bfloat16_as_ushort(l0) |
                    ((unsigned)__bfloat16_as_ushort(l1) << 16);
        }
        *(uint4*)(dh + r) = make_uint4(hu[0], hu[1], hu[2], hu[3]);
        *(uint4*)(dl + r) = make_uint4(lu[0], lu[1], lu[2], lu[3]);
    }
}

// ============================================================
// K4: mma.sync bf16-split GEMM  part[z] = sig @ W^T (128x128 tiles)
// grid (2, 2, SPLITK) = 148 CTAs (one full wave), 256 thr
// ============================================================
__global__ __launch_bounds__(256) void k_mma()
{
    extern __shared__ __align__(16) char smem[];
    uint32_t sb = smem_u32(smem);
    int tid = threadIdx.x, wid = tid >> 5, lane = tid & 31;
    int q = lane >> 2, rs = lane & 3;
    int wm = wid & 3, wn = wid >> 2;
    int n0 = blockIdx.x * 128, o0 = blockIdx.y * 128, z = blockIdx.z;
    int kb = z * KCH;

    const __nv_bfloat16* gb0 = g_shi + (size_t)n0 * SIGS;
    const __nv_bfloat16* gb1 = g_slo + (size_t)n0 * SIGS;
    const __nv_bfloat16* gb2 = g_whi + (size_t)o0 * SIGS;
    const __nv_bfloat16* gb3 = g_wlo + (size_t)o0 * SIGS;

    auto issue = [&](int c) {
        uint32_t sdst = sb + (c & 1) * BUF_B;
        int k0 = kb + c * 32;
        #pragma unroll
        for (int i = 0; i < 8; i++) {
            int idx = tid + 256 * i;
            int arr = idx >> 9;
            int r = (idx >> 2) & 127;
            int seg = idx & 3;
            const __nv_bfloat16* gp =
                (arr == 0 ? gb0 : arr == 1 ? gb1 : arr == 2 ? gb2 : gb3)
                + (size_t)r * SIGS + k0 + seg * 8;
            uint32_t sp = sdst + arr * ARR_B + r * (RST * 2) + seg * 16;
            asm volatile("cp.async.cg.shared.global [%0], [%1], 16;"
                         :: "r"(sp), "l"(gp));
        }
        asm volatile("cp.async.commit_group;" ::: "memory");
    };

    float acc[2][8][4];
    #pragma unroll
    for (int mt = 0; mt < 2; mt++)
        #pragma unroll
        for (int nt = 0; nt < 8; nt++)
            #pragma unroll
            for (int j = 0; j < 4; j++) acc[mt][nt][j] = 0.f;

    issue(0);
    issue(1);

    for (int c = 0; c < NCH; c++) {
        if (c + 2 < NCH)
            asm volatile("cp.async.wait_group 1;" ::: "memory");
        else
            asm volatile("cp.async.wait_group 0;" ::: "memory");
        __syncthreads();

        const __nv_bfloat16* Ah =
            (const __nv_bfloat16*)(smem + (c & 1) * BUF_B);
        const __nv_bfloat16* Al = Ah + 128 * RST;
        const __nv_bfloat16* Bh = Al + 128 * RST;
        const __nv_bfloat16* Bl = Bh + 128 * RST;

        #pragma unroll
        for (int kk = 0; kk < 2; kk++) {
            int col = 2 * rs + 16 * kk;
            uint32_t af[2][2][4];
            #pragma unroll
            for (int mt = 0; mt < 2; mt++) {
                int r0 = 32 * wm + 16 * mt + q;
                af[mt][0][0] = ld32h(Ah + r0 * RST + col);
                af[mt][0][1] = ld32h(Ah + (r0 + 8) * RST + col);
                af[mt][0][2] = ld32h(Ah + r0 * RST + col + 8);
                af[mt][0][3] = ld32h(Ah + (r0 + 8) * RST + col + 8);
                af[mt][1][0] = ld32h(Al + r0 * RST + col);
                af[mt][1][1] = ld32h(Al + (r0 + 8) * RST + col);
                af[mt][1][2] = ld32h(Al + r0 * RST + col + 8);
                af[mt][1][3] = ld32h(Al + (r0 + 8) * RST + col + 8);
            }
            uint32_t bfr[8][2][2];
            #pragma unroll
            for (int nt = 0; nt < 8; nt++) {
                int rn = 64 * wn + 8 * nt + q;
                bfr[nt][0][0] = ld32h(Bh + rn * RST + col);
                bfr[nt][0][1] = ld32h(Bh + rn * RST + col + 8);
                bfr[nt][1][0] = ld32h(Bl + rn * RST + col);
                bfr[nt][1][1] = ld32h(Bl + rn * RST + col + 8);
            }
            #pragma unroll
            for (int mt = 0; mt < 2; mt++)
                #pragma unroll
                for (int nt = 0; nt < 8; nt++) {
                    mma16816(acc[mt][nt], af[mt][0], bfr[nt][0]);
                    mma16816(acc[mt][nt], af[mt][0], bfr[nt][1]);
                    mma16816(acc[mt][nt], af[mt][1], bfr[nt][0]);
                }
        }
        __syncthreads();
        if (c + 2 < NCH) issue(c + 2);
    }

    // epilogue -> g_part[z]
    float* pz = g_part + ((size_t)z * 256 + n0 + 32 * wm) * 256 + o0 + 64 * wn;
    #pragma unroll
    for (int mt = 0; mt < 2; mt++) {
        #pragma unroll
        for (int nt = 0; nt < 8; nt++) {
            int m = 16 * mt + q;
            int cc = 8 * nt + 2 * rs;
            float2 v01 = make_float2(acc[mt][nt][0], acc[mt][nt][1]);
            float2 v23 = make_float2(acc[mt][nt][2], acc[mt][nt][3]);
            *(float2*)&pz[(size_t)m * 256 + cc] = v01;
            *(float2*)&pz[(size_t)(m + 8) * 256 + cc] = v23;
        }
    }
}

// ============================================================
// K5: reduce splitK partials + bias
// ============================================================
__global__ void k_red(const float* __restrict__ lb, float* __restrict__ out)
{
    int n = blockIdx.x, o = threadIdx.x;
    float s = lb[o];
    #pragma unroll 4
    for (int z = 0; z < SPLITK; z++)
        s += g_part[((size_t)z * 256 + n) * 256 + o];
    out[n * 256 + o] = s;
}

// ============================================================
extern "C" void kernel_launch(void* const* d_in, const int* in_sizes, int n_in,
                              void* d_out, int out_size)
{
    const float* q  = (const float*)d_in[0];
    const float* w1 = (const float*)d_in[4];
    const float* b1 = (const float*)d_in[5];
    const float* w2 = (const float*)d_in[6];
    const float* b2 = (const float*)d_in[7];
    const float* lw = (const float*)d_in[8];
    const float* lb = (const float*)d_in[9];
    float* out = (float*)d_out;

    cudaFuncSetAttribute(k_front, cudaFuncAttributeMaxDynamicSharedMemorySize,
                         24256 * 4);
    cudaFuncSetAttribute(k_mma, cudaFuncAttributeMaxDynamicSharedMemorySize,
                         2 * BUF_B);
    k_front<<<NB, 256, 24256 * 4>>>(q, w1, b1, w2, b2);
    k_sig<<<NB, 256>>>();
    k_wprep<<<SIGS / 32, 256>>>(lw);
    k_mma<<<dim3(2, 2, SPLITK), 256, 2 * BUF_B>>>();
    k_red<<<256, 256>>>(lb, out);
}